// round 8
// baseline (speedup 1.0000x reference)
#include <cuda_runtime.h>
#include <cuda_fp16.h>
#include <math.h>
#include <stdint.h>

// Problem constants
#define B_ 8192
#define F_ 1024
#define U_ 512
#define O_ 3
#define A_ 6
#define H_ 4
#define HD_ 128

typedef __half h16;
#define BU_ ((size_t)B_ * U_)
#define UF_ ((size_t)U_ * F_)

// ===========================================================================
// Scratch (device globals) — all activations fp16
// ===========================================================================
__device__ __align__(128) h16 g_feat[(size_t)B_ * F_];
__device__ __align__(128) h16 g_cat[(size_t)B_ * 2 * U_];     // [agent_latent | attn_out]
__device__ __align__(128) h16 g_opp[(size_t)O_ * B_ * U_];
__device__ __align__(128) h16 g_attn[(size_t)B_ * U_];
__device__ __align__(128) h16 g_q[(size_t)B_ * U_];
__device__ __align__(128) h16 g_kv[(size_t)O_ * B_ * 2 * U_]; // [O][B][k|v]
__device__ __align__(128) h16 g_ah[(size_t)B_ * U_];
__device__ __align__(128) h16 g_oh[(size_t)O_ * B_ * U_];
// weights (fp16); Wbig = [W_al | W_ol(3)] packed, z-stride U*F
__device__ __align__(128) h16 g_Wbig[(size_t)4 * U_ * F_];
__device__ __align__(128) h16 g_Win[(size_t)3 * U_ * U_];
__device__ __align__(128) h16 g_Wout[(size_t)U_ * U_];
__device__ __align__(128) h16 g_Wah[(size_t)U_ * 2 * U_];
__device__ __align__(128) h16 g_Woh[(size_t)O_ * U_ * U_];

// ===========================================================================
// PTX helpers
// ===========================================================================
__device__ __forceinline__ uint32_t smem_u32(const void* p) {
    uint32_t a;
    asm("{ .reg .u64 t; cvta.to.shared.u64 t, %1; cvt.u32.u64 %0, t; }"
        : "=r"(a) : "l"(p));
    return a;
}
__device__ __forceinline__ void cp16(uint32_t s, const void* g) {
    asm volatile("cp.async.cg.shared.global [%0], [%1], 16;" :: "r"(s), "l"(g));
}
#define CP_COMMIT() asm volatile("cp.async.commit_group;" ::: "memory")
#define CP_WAIT0()  asm volatile("cp.async.wait_group 0;" ::: "memory")
#define CP_WAIT1()  asm volatile("cp.async.wait_group 1;" ::: "memory")
#define CP_WAIT2()  asm volatile("cp.async.wait_group 2;" ::: "memory")

__device__ __forceinline__ void ldsm4(uint32_t* r, uint32_t addr) {
    asm volatile("ldmatrix.sync.aligned.m8n8.x4.shared.b16 {%0,%1,%2,%3}, [%4];"
                 : "=r"(r[0]), "=r"(r[1]), "=r"(r[2]), "=r"(r[3]) : "r"(addr));
}
__device__ __forceinline__ void mma_f16(float* c, const uint32_t* a, const uint32_t* b) {
    asm volatile("mma.sync.aligned.m16n8k16.row.col.f32.f16.f16.f32 "
                 "{%0,%1,%2,%3}, {%4,%5,%6,%7}, {%8,%9}, {%0,%1,%2,%3};"
                 : "+f"(c[0]), "+f"(c[1]), "+f"(c[2]), "+f"(c[3])
                 : "r"(a[0]), "r"(a[1]), "r"(a[2]), "r"(a[3]),
                   "r"(b[0]), "r"(b[1]));
}
__device__ __forceinline__ void unpack8(uint4 u, float* out) {
    const __half2* h = (const __half2*)&u;
#pragma unroll
    for (int j = 0; j < 4; j++) {
        float2 f = __half22float2(h[j]);
        out[2 * j] = f.x; out[2 * j + 1] = f.y;
    }
}
__device__ __forceinline__ float4 load_h4(const h16* p) {
    uint2 u = *(const uint2*)p;
    const __half2* h = (const __half2*)&u;
    float2 a = __half22float2(h[0]), b = __half22float2(h[1]);
    return make_float4(a.x, a.y, b.x, b.y);
}

// ===========================================================================
// One-shot convert: features + all weights, flat index + segment chain
// ===========================================================================
#define CN0 ((int)((size_t)B_ * F_ / 4))
#define CN1 ((int)(UF_ / 4))
#define CN2 ((int)(3 * UF_ / 4))
#define CN3 ((int)(3 * (size_t)U_ * U_ / 4))
#define CN4 ((int)((size_t)U_ * U_ / 4))
#define CN5 ((int)(2 * (size_t)U_ * U_ / 4))
#define CN6 ((int)(3 * (size_t)U_ * U_ / 4))
#define CTOT (CN0 + CN1 + CN2 + CN3 + CN4 + CN5 + CN6)

__global__ void convert_all(const float* __restrict__ f,
                            const float* __restrict__ wal,
                            const float* __restrict__ wol,
                            const float* __restrict__ win,
                            const float* __restrict__ wout,
                            const float* __restrict__ wah,
                            const float* __restrict__ woh)
{
    int i = blockIdx.x * blockDim.x + threadIdx.x;
    if (i >= CTOT) return;
    const float* src; h16* dst; int off;
    if (i < CN0)                 { src = f;    dst = g_feat;        off = i; }
    else if ((i -= CN0) < CN1)   { src = wal;  dst = g_Wbig;        off = i; }
    else if ((i -= CN1) < CN2)   { src = wol;  dst = g_Wbig + UF_;  off = i; }
    else if ((i -= CN2) < CN3)   { src = win;  dst = g_Win;         off = i; }
    else if ((i -= CN3) < CN4)   { src = wout; dst = g_Wout;        off = i; }
    else if ((i -= CN4) < CN5)   { src = wah;  dst = g_Wah;         off = i; }
    else                         { src = woh;  dst = g_Woh;         off = i - CN5; }
    float4 x = ((const float4*)src)[off];
    h16 h[4] = {__float2half_rn(x.x), __float2half_rn(x.y),
                __float2half_rn(x.z), __float2half_rn(x.w)};
    ((uint2*)dst)[off] = *(uint2*)h;
}

// ===========================================================================
// 1-pass fp16 HMMA GEMM: C(h16) = act((A @ W^T + bias) * scale)
// CTA 128x128, 8 warps (4Mx2N), K stage 32, 4-stage cp.async ring, occ 2.
// MERGE: z=0 -> Ch/ldcb (cat), z>0 -> g_opp + (z-1)*BU, ldc=U_.
// ===========================================================================
#define MT 128
#define NT 128
#define KB 32
#define RSTRIDE 80
#define COMP_BYTES (128 * RSTRIDE)
#define OFF_A 0
#define OFF_W COMP_BYTES
#define STG_BYTES (2 * COMP_BYTES)
#define NSTAGE 4
#define GEMM_SMEM (1024 + NSTAGE * STG_BYTES)

__device__ __forceinline__ void load_stage_async(
    uint32_t st, int tid,
    const h16* __restrict__ A, int lda, int mtile,
    const h16* __restrict__ W, int ldw, int ntile, int k0)
{
#pragma unroll
    for (int i = 0; i < 2; i++) {
        int idx = tid + i * 256;
        int r = idx >> 2, c = idx & 3;
        uint32_t so = (uint32_t)(r * RSTRIDE + c * 16);
        cp16(st + OFF_A + so, A + (size_t)(mtile + r) * lda + k0 + c * 8);
        cp16(st + OFF_W + so, W + (size_t)(ntile + r) * ldw + k0 + c * 8);
    }
    CP_COMMIT();
}

template <bool ELU_, bool MERGE>
__global__ void __launch_bounds__(256, 2)
gemm_mma(const h16* __restrict__ A, int lda, unsigned long long Az,
         const h16* __restrict__ W, int ldw, unsigned long long Wz,
         const float* __restrict__ bias, int bz, float scale,
         h16* __restrict__ Ch, int ldcb, unsigned long long Cbz,
         const float* __restrict__ bias_ol,
         int K)
{
    extern __shared__ __align__(128) char smem[];
    const int z = blockIdx.z;
    A += (size_t)z * Az;
    W += (size_t)z * Wz;

    const float* bptr = bias + (size_t)z * bz;
    h16* cptr = Ch + (size_t)z * Cbz;
    int ldc = ldcb;
    if (MERGE && z > 0) {
        bptr = bias_ol + (size_t)(z - 1) * U_;
        cptr = g_opp + (size_t)(z - 1) * BU_;
        ldc = U_;
    }

    float* bias_s = (float*)smem;
    const uint32_t st0 = smem_u32(smem + 1024);

    const int tid = threadIdx.x, lane = tid & 31, wid = tid >> 5;
    const int wm = wid & 3, wn = wid >> 2;
    const int mtile = blockIdx.y * MT;
    const int ntile = blockIdx.x * NT;

    if (tid < NT) bias_s[tid] = bptr[ntile + tid];

    float acc[2][8][4];
#pragma unroll
    for (int i = 0; i < 2; i++)
#pragma unroll
        for (int j = 0; j < 8; j++)
#pragma unroll
            for (int t = 0; t < 4; t++) acc[i][j][t] = 0.f;

    const int nc = K / KB;

    load_stage_async(st0, tid, A, lda, mtile, W, ldw, ntile, 0);
    if (nc > 1)
        load_stage_async(st0 + STG_BYTES, tid, A, lda, mtile, W, ldw, ntile, KB);
    if (nc > 2)
        load_stage_async(st0 + 2 * STG_BYTES, tid, A, lda, mtile, W, ldw, ntile, 2 * KB);

    const uint32_t a_row = (uint32_t)(lane & 15);
    const uint32_t a_koff = (uint32_t)((lane >> 4) * 16);
    const uint32_t b_row = (uint32_t)(((lane >> 4) * 8) + (lane & 7));
    const uint32_t b_koff = (uint32_t)(((lane >> 3) & 1) * 16);

    int sidx = 0;
    for (int c = 0; c < nc; ++c) {
        const int rem = nc - c - 1;
        if (rem >= 2)      CP_WAIT2();
        else if (rem == 1) CP_WAIT1();
        else               CP_WAIT0();
        __syncthreads();
        if (c + 3 < nc) {
            int nidx = sidx + 3; if (nidx >= NSTAGE) nidx -= NSTAGE;
            load_stage_async(st0 + nidx * STG_BYTES, tid,
                             A, lda, mtile, W, ldw, ntile, (c + 3) * KB);
        }
        const uint32_t cur = st0 + sidx * STG_BYTES;
#pragma unroll
        for (int kc = 0; kc < 2; kc++) {
            uint32_t af[2][4], wf[4][4];
#pragma unroll
            for (int mt = 0; mt < 2; mt++) {
                uint32_t row = wm * 32 + mt * 16 + a_row;
                ldsm4(af[mt], cur + OFF_A + row * RSTRIDE + kc * 32 + a_koff);
            }
#pragma unroll
            for (int q = 0; q < 4; q++) {
                uint32_t row = wn * 64 + q * 16 + b_row;
                ldsm4(wf[q], cur + OFF_W + row * RSTRIDE + kc * 32 + b_koff);
            }
#pragma unroll
            for (int mt = 0; mt < 2; mt++)
#pragma unroll
                for (int q = 0; q < 4; q++)
#pragma unroll
                    for (int s = 0; s < 2; s++)
                        mma_f16(acc[mt][2 * q + s], af[mt], &wf[q][2 * s]);
        }
        if (++sidx >= NSTAGE) sidx = 0;
    }

    // epilogue (h16 only)
    const int g = lane >> 2, tg = lane & 3;
#pragma unroll
    for (int mt = 0; mt < 2; mt++) {
        const int m0 = mtile + wm * 32 + mt * 16 + g;
#pragma unroll
        for (int n8 = 0; n8 < 8; n8++) {
            const int nl = wn * 64 + n8 * 8 + tg * 2;
            const int n = ntile + nl;
            const float b0 = bias_s[nl], b1 = bias_s[nl + 1];
            float x0 = (acc[mt][n8][0] + b0) * scale;
            float x1 = (acc[mt][n8][1] + b1) * scale;
            float y0 = (acc[mt][n8][2] + b0) * scale;
            float y1 = (acc[mt][n8][3] + b1) * scale;
            if (ELU_) {
                x0 = x0 > 0.f ? x0 : expm1f(x0);
                x1 = x1 > 0.f ? x1 : expm1f(x1);
                y0 = y0 > 0.f ? y0 : expm1f(y0);
                y1 = y1 > 0.f ? y1 : expm1f(y1);
            }
            union { h16 h[2]; uint32_t u; } p;
            p.h[0] = __float2half_rn(x0); p.h[1] = __float2half_rn(x1);
            *(uint32_t*)(cptr + (size_t)m0 * ldc + n) = p.u;
            p.h[0] = __float2half_rn(y0); p.h[1] = __float2half_rn(y1);
            *(uint32_t*)(cptr + (size_t)(m0 + 8) * ldc + n) = p.u;
        }
    }
}

// ===========================================================================
// Attention — fp16 q/kv inputs, fp16 attn output
// ===========================================================================
__global__ void attention_kernel(const h16* __restrict__ q,
                                 const h16* __restrict__ kv,
                                 h16* __restrict__ attn,
                                 float* __restrict__ infl)
{
    const int b = blockIdx.x;
    const int tid = threadIdx.x;
    const int h = tid >> 5;
    const int lane = tid & 31;
    __shared__ float sw[H_][O_];

    const size_t base = (size_t)b * U_ + (size_t)h * HD_;
    const float4 qv = load_h4(q + base + lane * 4);

    float s[O_];
#pragma unroll
    for (int o = 0; o < O_; o++) {
        const size_t kb = ((size_t)o * B_ + b) * (2 * U_) + (size_t)h * HD_;
        const float4 kvv = load_h4(kv + kb + lane * 4);
        float d = qv.x * kvv.x + qv.y * kvv.y + qv.z * kvv.z + qv.w * kvv.w;
#pragma unroll
        for (int off = 16; off > 0; off >>= 1)
            d += __shfl_xor_sync(0xffffffffu, d, off);
        s[o] = d;
    }
    const float m = fmaxf(s[0], fmaxf(s[1], s[2]));
    const float e0 = expf(s[0] - m), e1 = expf(s[1] - m), e2 = expf(s[2] - m);
    const float inv = 1.f / (e0 + e1 + e2);
    const float w[O_] = {e0 * inv, e1 * inv, e2 * inv};

    float4 a = make_float4(0.f, 0.f, 0.f, 0.f);
#pragma unroll
    for (int o = 0; o < O_; o++) {
        const size_t vb = ((size_t)o * B_ + b) * (2 * U_) + U_ + (size_t)h * HD_;
        const float4 vv = load_h4(kv + vb + lane * 4);
        a.x = fmaf(w[o], vv.x, a.x);
        a.y = fmaf(w[o], vv.y, a.y);
        a.z = fmaf(w[o], vv.z, a.z);
        a.w = fmaf(w[o], vv.w, a.w);
    }
    {
        union { h16 h[4]; uint2 u; } uh;
        uh.h[0] = __float2half_rn(a.x); uh.h[1] = __float2half_rn(a.y);
        uh.h[2] = __float2half_rn(a.z); uh.h[3] = __float2half_rn(a.w);
        *(uint2*)(attn + base + lane * 4) = uh.u;
    }

    if (lane == 0) { sw[h][0] = w[0]; sw[h][1] = w[1]; sw[h][2] = w[2]; }
    __syncthreads();
    if (tid < O_)
        infl[(size_t)b * O_ + tid] =
            0.25f * (sw[0][tid] + sw[1][tid] + sw[2][tid] + sw[3][tid]);
}

// ===========================================================================
// Fused skinny heads — one warp per row, fp16 activations, fp32 weights
// ===========================================================================
__global__ void skinny_agent(const h16* __restrict__ ah,
                             const float* __restrict__ Wp, const float* __restrict__ bp,
                             const float* __restrict__ Wv, const float* __restrict__ bv,
                             float* __restrict__ pol, float* __restrict__ val)
{
    const int wid = threadIdx.x >> 5, lane = threadIdx.x & 31;
    const int b = blockIdx.x * 8 + wid;
    const uint4* x4 = (const uint4*)(ah + (size_t)b * U_);
    float xs[16];
    unpack8(x4[lane], xs);
    unpack8(x4[lane + 32], xs + 8);
#pragma unroll
    for (int n = 0; n < 7; n++) {
        const float4* w4 = (const float4*)((n < 6) ? (Wp + (size_t)n * U_) : Wv);
        float d = 0.f;
        float wf[8];
        *(float4*)(wf)     = w4[2 * lane];
        *(float4*)(wf + 4) = w4[2 * lane + 1];
#pragma unroll
        for (int t = 0; t < 8; t++) d += xs[t] * wf[t];
        *(float4*)(wf)     = w4[2 * (lane + 32)];
        *(float4*)(wf + 4) = w4[2 * (lane + 32) + 1];
#pragma unroll
        for (int t = 0; t < 8; t++) d += xs[8 + t] * wf[t];
#pragma unroll
        for (int off = 16; off > 0; off >>= 1) d += __shfl_xor_sync(~0u, d, off);
        if (lane == 0) {
            if (n < 6) pol[(size_t)b * A_ + n] = d + bp[n];
            else       val[b] = d + bv[0];
        }
    }
}

__global__ void skinny_opp(const h16* __restrict__ oh,
                           const float* __restrict__ W_op, const float* __restrict__ b_op,
                           const float* __restrict__ W_ov, const float* __restrict__ b_ov,
                           float* __restrict__ pol, float* __restrict__ val)
{
    const int wid = threadIdx.x >> 5, lane = threadIdx.x & 31;
    const int b = blockIdx.x * 8 + wid;
    const int o = blockIdx.y;
    const uint4* x4 = (const uint4*)(oh + ((size_t)o * B_ + b) * U_);
    float xs[16];
    unpack8(x4[lane], xs);
    unpack8(x4[lane + 32], xs + 8);
    const float* Wp = W_op + (size_t)o * A_ * U_;
    const float* Wv = W_ov + (size_t)o * U_;
#pragma unroll
    for (int n = 0; n < 7; n++) {
        const float4* w4 = (const float4*)((n < 6) ? (Wp + (size_t)n * U_) : Wv);
        float d = 0.f;
        float wf[8];
        *(float4*)(wf)     = w4[2 * lane];
        *(float4*)(wf + 4) = w4[2 * lane + 1];
#pragma unroll
        for (int t = 0; t < 8; t++) d += xs[t] * wf[t];
        *(float4*)(wf)     = w4[2 * (lane + 32)];
        *(float4*)(wf + 4) = w4[2 * (lane + 32) + 1];
#pragma unroll
        for (int t = 0; t < 8; t++) d += xs[8 + t] * wf[t];
#pragma unroll
        for (int off = 16; off > 0; off >>= 1) d += __shfl_xor_sync(~0u, d, off);
        if (lane == 0) {
            if (n < 6) pol[(size_t)b * (O_ * A_) + o * A_ + n] = d + b_op[o * A_ + n];
            else       val[(size_t)b * O_ + o] = d + b_ov[o];
        }
    }
}

// ===========================================================================
extern "C" void kernel_launch(void* const* d_in, const int* in_sizes, int n_in,
                              void* d_out, int out_size)
{
    const float* features = (const float*)d_in[0];
    const float* W_al = (const float*)d_in[1];
    const float* b_al = (const float*)d_in[2];
    const float* W_in = (const float*)d_in[3];
    const float* b_in = (const float*)d_in[4];
    const float* W_out = (const float*)d_in[5];
    const float* b_out = (const float*)d_in[6];
    const float* W_ah = (const float*)d_in[7];
    const float* b_ah = (const float*)d_in[8];
    const float* W_ap = (const float*)d_in[9];
    const float* b_ap = (const float*)d_in[10];
    const float* W_av = (const float*)d_in[11];
    const float* b_av = (const float*)d_in[12];
    const float* W_ol = (const float*)d_in[13];
    const float* b_ol = (const float*)d_in[14];
    const float* W_oh = (const float*)d_in[15];
    const float* b_oh = (const float*)d_in[16];
    const float* W_op = (const float*)d_in[17];
    const float* b_op = (const float*)d_in[18];
    const float* W_ov = (const float*)d_in[19];
    const float* b_ov = (const float*)d_in[20];
    float* out = (float*)d_out;

    h16 *feat, *cat, *opp, *attn, *q, *kv, *ah, *oh;
    h16 *Wbig, *Win, *Wout, *Wah, *Woh;
    cudaGetSymbolAddress((void**)&feat, g_feat);
    cudaGetSymbolAddress((void**)&cat, g_cat);
    cudaGetSymbolAddress((void**)&opp, g_opp);
    cudaGetSymbolAddress((void**)&attn, g_attn);
    cudaGetSymbolAddress((void**)&q, g_q);
    cudaGetSymbolAddress((void**)&kv, g_kv);
    cudaGetSymbolAddress((void**)&ah, g_ah);
    cudaGetSymbolAddress((void**)&oh, g_oh);
    cudaGetSymbolAddress((void**)&Wbig, g_Wbig);
    cudaGetSymbolAddress((void**)&Win, g_Win);
    cudaGetSymbolAddress((void**)&Wout, g_Wout);
    cudaGetSymbolAddress((void**)&Wah, g_Wah);
    cudaGetSymbolAddress((void**)&Woh, g_Woh);

    cudaFuncSetAttribute(gemm_mma<true, true>,
                         cudaFuncAttributeMaxDynamicSharedMemorySize, GEMM_SMEM);
    cudaFuncSetAttribute(gemm_mma<false, false>,
                         cudaFuncAttributeMaxDynamicSharedMemorySize, GEMM_SMEM);
    cudaFuncSetAttribute(gemm_mma<true, false>,
                         cudaFuncAttributeMaxDynamicSharedMemorySize, GEMM_SMEM);

    const float qscale = 0.08838834764831845f;  // 1/sqrt(128)

    float* out_agent_policy = out;
    float* out_agent_value  = out + (size_t)B_ * A_;
    float* out_opp_policy   = out_agent_value + B_;
    float* out_opp_value    = out_opp_policy + (size_t)B_ * O_ * A_;
    float* out_infl         = out_opp_value + (size_t)B_ * O_;

    const dim3 gb(256);

    // 0) all converts in one launch
    convert_all<<<(CTOT + 255) / 256, 256>>>(features, W_al, W_ol, W_in,
                                             W_out, W_ah, W_oh);
    // 1+2) agent_latent (z=0 -> cat[:, :U]) + opp_lat (z=1..3), merged, K=F
    gemm_mma<true, true><<<dim3(4, 64, 4), gb, GEMM_SMEM>>>(
        feat, F_, 0ull, Wbig, F_, (unsigned long long)UF_, b_al, 0, 1.f,
        cat, 2 * U_, 0ull, b_ol, F_);
    // 3) q = agent_latent @ Wq^T (reads cat[:, :U] only): K = U_ (!)
    gemm_mma<false, false><<<dim3(4, 64, 1), gb, GEMM_SMEM>>>(
        cat, 2 * U_, 0ull, Win, U_, 0ull, b_in, 0, qscale,
        q, U_, 0ull, nullptr, U_);
    // 4) k+v fused (N=1024), z=3, K=U
    gemm_mma<false, false><<<dim3(8, 64, 3), gb, GEMM_SMEM>>>(
        opp, U_, (unsigned long long)BU_,
        Win + (size_t)U_ * U_, U_, 0ull, b_in + U_, 0, 1.f,
        kv, 2 * U_, (unsigned long long)B_ * 2 * U_, nullptr, U_);
    // 5) attention
    attention_kernel<<<B_, 128>>>(q, kv, attn, out_infl);
    // 6) attn_out -> cat[:, U:], K=U
    gemm_mma<false, false><<<dim3(4, 64, 1), gb, GEMM_SMEM>>>(
        attn, U_, 0ull, Wout, U_, 0ull, b_out, 0, 1.f,
        cat + U_, 2 * U_, 0ull, nullptr, U_);
    // 7) agent_head, K = 2U (reads full cat — both halves written this run)
    gemm_mma<true, false><<<dim3(4, 64, 1), gb, GEMM_SMEM>>>(
        cat, 2 * U_, 0ull, Wah, 2 * U_, 0ull, b_ah, 0, 1.f,
        ah, U_, 0ull, nullptr, 2 * U_);
    // 8) agent policy + value
    skinny_agent<<<B_ / 8, 256>>>(ah, W_ap, b_ap, W_av, b_av,
                                  out_agent_policy, out_agent_value);
    // 9) opp_heads (z=3), K=U
    gemm_mma<true, false><<<dim3(4, 64, 3), gb, GEMM_SMEM>>>(
        opp, U_, (unsigned long long)BU_,
        Woh, U_, (unsigned long long)((size_t)U_ * U_), b_oh, U_, 1.f,
        oh, U_, (unsigned long long)BU_, nullptr, U_);
    // 10) opponent policies + values
    skinny_opp<<<dim3(B_ / 8, 3), 256>>>(oh, W_op, b_op, W_ov, b_ov,
                                         out_opp_policy, out_opp_value);
}

// round 9
// speedup vs baseline: 1.4069x; 1.4069x over previous
#include <cuda_runtime.h>
#include <cuda_fp16.h>
#include <math.h>
#include <stdint.h>

// Problem constants
#define B_ 8192
#define F_ 1024
#define U_ 512
#define O_ 3
#define A_ 6
#define H_ 4
#define HD_ 128

typedef __half h16;
#define BU_ ((size_t)B_ * U_)
#define UF_ ((size_t)U_ * F_)

// ===========================================================================
// Scratch (device globals) — all activations fp16
// ===========================================================================
__device__ __align__(128) h16 g_feat[(size_t)B_ * F_];
__device__ __align__(128) h16 g_cat[(size_t)B_ * 2 * U_];     // [agent_latent | attn_out]
__device__ __align__(128) h16 g_opp[(size_t)O_ * B_ * U_];
__device__ __align__(128) h16 g_attn[(size_t)B_ * U_];
__device__ __align__(128) h16 g_q[(size_t)B_ * U_];
__device__ __align__(128) h16 g_kv[(size_t)O_ * B_ * 2 * U_]; // [O][B][k|v]
__device__ __align__(128) h16 g_ah[(size_t)B_ * U_];
__device__ __align__(128) h16 g_oh[(size_t)O_ * B_ * U_];
// weights (fp16); Wbig = [W_al | W_ol(3)] packed, z-stride U*F
__device__ __align__(128) h16 g_Wbig[(size_t)4 * U_ * F_];
__device__ __align__(128) h16 g_Win[(size_t)3 * U_ * U_];
__device__ __align__(128) h16 g_Wout[(size_t)U_ * U_];
__device__ __align__(128) h16 g_Wah[(size_t)U_ * 2 * U_];
__device__ __align__(128) h16 g_Woh[(size_t)O_ * U_ * U_];

// ===========================================================================
// PTX helpers
// ===========================================================================
__device__ __forceinline__ uint32_t smem_u32(const void* p) {
    uint32_t a;
    asm("{ .reg .u64 t; cvta.to.shared.u64 t, %1; cvt.u32.u64 %0, t; }"
        : "=r"(a) : "l"(p));
    return a;
}
__device__ __forceinline__ void cp16(uint32_t s, const void* g) {
    asm volatile("cp.async.cg.shared.global [%0], [%1], 16;" :: "r"(s), "l"(g));
}
#define CP_COMMIT() asm volatile("cp.async.commit_group;" ::: "memory")
#define CP_WAIT0()  asm volatile("cp.async.wait_group 0;" ::: "memory")
#define CP_WAIT1()  asm volatile("cp.async.wait_group 1;" ::: "memory")

__device__ __forceinline__ void ldsm4(uint32_t* r, uint32_t addr) {
    asm volatile("ldmatrix.sync.aligned.m8n8.x4.shared.b16 {%0,%1,%2,%3}, [%4];"
                 : "=r"(r[0]), "=r"(r[1]), "=r"(r[2]), "=r"(r[3]) : "r"(addr));
}
__device__ __forceinline__ void mma_f16(float* c, const uint32_t* a, const uint32_t* b) {
    asm volatile("mma.sync.aligned.m16n8k16.row.col.f32.f16.f16.f32 "
                 "{%0,%1,%2,%3}, {%4,%5,%6,%7}, {%8,%9}, {%0,%1,%2,%3};"
                 : "+f"(c[0]), "+f"(c[1]), "+f"(c[2]), "+f"(c[3])
                 : "r"(a[0]), "r"(a[1]), "r"(a[2]), "r"(a[3]),
                   "r"(b[0]), "r"(b[1]));
}
__device__ __forceinline__ void unpack8(uint4 u, float* out) {
    const __half2* h = (const __half2*)&u;
#pragma unroll
    for (int j = 0; j < 4; j++) {
        float2 f = __half22float2(h[j]);
        out[2 * j] = f.x; out[2 * j + 1] = f.y;
    }
}
__device__ __forceinline__ float4 load_h4(const h16* p) {
    uint2 u = *(const uint2*)p;
    const __half2* h = (const __half2*)&u;
    float2 a = __half22float2(h[0]), b = __half22float2(h[1]);
    return make_float4(a.x, a.y, b.x, b.y);
}

// ===========================================================================
// One-shot convert: features + all weights, flat index + segment chain
// ===========================================================================
#define CN0 ((int)((size_t)B_ * F_ / 4))
#define CN1 ((int)(UF_ / 4))
#define CN2 ((int)(3 * UF_ / 4))
#define CN3 ((int)(3 * (size_t)U_ * U_ / 4))
#define CN4 ((int)((size_t)U_ * U_ / 4))
#define CN5 ((int)(2 * (size_t)U_ * U_ / 4))
#define CN6 ((int)(3 * (size_t)U_ * U_ / 4))
#define CTOT (CN0 + CN1 + CN2 + CN3 + CN4 + CN5 + CN6)

__global__ void convert_all(const float* __restrict__ f,
                            const float* __restrict__ wal,
                            const float* __restrict__ wol,
                            const float* __restrict__ win,
                            const float* __restrict__ wout,
                            const float* __restrict__ wah,
                            const float* __restrict__ woh)
{
    int i = blockIdx.x * blockDim.x + threadIdx.x;
    if (i >= CTOT) return;
    const float* src; h16* dst; int off;
    if (i < CN0)                 { src = f;    dst = g_feat;        off = i; }
    else if ((i -= CN0) < CN1)   { src = wal;  dst = g_Wbig;        off = i; }
    else if ((i -= CN1) < CN2)   { src = wol;  dst = g_Wbig + UF_;  off = i; }
    else if ((i -= CN2) < CN3)   { src = win;  dst = g_Win;         off = i; }
    else if ((i -= CN3) < CN4)   { src = wout; dst = g_Wout;        off = i; }
    else if ((i -= CN4) < CN5)   { src = wah;  dst = g_Wah;         off = i; }
    else                         { src = woh;  dst = g_Woh;         off = i - CN5; }
    float4 x = ((const float4*)src)[off];
    h16 h[4] = {__float2half_rn(x.x), __float2half_rn(x.y),
                __float2half_rn(x.z), __float2half_rn(x.w)};
    ((uint2*)dst)[off] = *(uint2*)h;
}

// ===========================================================================
// 1-pass fp16 HMMA GEMM: C(h16) = act((A @ W^T + bias) * scale)
// CTA 128x128, 8 warps (4Mx2N), K chunk = 64, 3-stage cp.async ring, occ 2.
// MERGE: z=0 -> Ch/ldcb (cat), z>0 -> g_opp + (z-1)*BU, ldc=U_.
// ===========================================================================
#define MT 128
#define NT 128
#define KB 64
#define RSTRIDE 144                      // 128B data + 16B pad (conflict-free)
#define COMP_BYTES (128 * RSTRIDE)       // 18432
#define OFF_A 0
#define OFF_W COMP_BYTES
#define STG_BYTES (2 * COMP_BYTES)       // 36864
#define NSTAGE 3
#define GEMM_SMEM (1024 + NSTAGE * STG_BYTES)   // 111616

__device__ __forceinline__ void load_stage_async(
    uint32_t st, int tid,
    const h16* __restrict__ A, int lda, int mtile,
    const h16* __restrict__ W, int ldw, int ntile, int k0)
{
#pragma unroll
    for (int i = 0; i < 4; i++) {        // A: 128 rows x 8 u4 = 1024 chunks
        int idx = tid + i * 256;
        int r = idx >> 3, c = idx & 7;
        uint32_t so = (uint32_t)(r * RSTRIDE + c * 16);
        cp16(st + OFF_A + so, A + (size_t)(mtile + r) * lda + k0 + c * 8);
    }
#pragma unroll
    for (int i = 0; i < 4; i++) {        // W: 128 rows x 8 u4
        int idx = tid + i * 256;
        int r = idx >> 3, c = idx & 7;
        uint32_t so = (uint32_t)(r * RSTRIDE + c * 16);
        cp16(st + OFF_W + so, W + (size_t)(ntile + r) * ldw + k0 + c * 8);
    }
    CP_COMMIT();
}

template <bool ELU_, bool MERGE>
__global__ void __launch_bounds__(256, 2)
gemm_mma(const h16* __restrict__ A, int lda, unsigned long long Az,
         const h16* __restrict__ W, int ldw, unsigned long long Wz,
         const float* __restrict__ bias, int bz, float scale,
         h16* __restrict__ Ch, int ldcb, unsigned long long Cbz,
         const float* __restrict__ bias_ol,
         int K)
{
    extern __shared__ __align__(128) char smem[];
    const int z = blockIdx.z;
    A += (size_t)z * Az;
    W += (size_t)z * Wz;

    const float* bptr = bias + (size_t)z * bz;
    h16* cptr = Ch + (size_t)z * Cbz;
    int ldc = ldcb;
    if (MERGE && z > 0) {
        bptr = bias_ol + (size_t)(z - 1) * U_;
        cptr = g_opp + (size_t)(z - 1) * BU_;
        ldc = U_;
    }

    float* bias_s = (float*)smem;
    const uint32_t st0 = smem_u32(smem + 1024);

    const int tid = threadIdx.x, lane = tid & 31, wid = tid >> 5;
    const int wm = wid & 3, wn = wid >> 2;
    const int mtile = blockIdx.y * MT;
    const int ntile = blockIdx.x * NT;

    if (tid < NT) bias_s[tid] = bptr[ntile + tid];

    float acc[2][8][4];
#pragma unroll
    for (int i = 0; i < 2; i++)
#pragma unroll
        for (int j = 0; j < 8; j++)
#pragma unroll
            for (int t = 0; t < 4; t++) acc[i][j][t] = 0.f;

    const int nc = K / KB;              // 8 (K=512) or 16 (K=1024)

    // prologue: 2 stages in flight
    load_stage_async(st0, tid, A, lda, mtile, W, ldw, ntile, 0);
    load_stage_async(st0 + STG_BYTES, tid, A, lda, mtile, W, ldw, ntile, KB);

    const uint32_t a_row = (uint32_t)(lane & 15);
    const uint32_t a_koff = (uint32_t)((lane >> 4) * 16);
    const uint32_t b_row = (uint32_t)(((lane >> 4) * 8) + (lane & 7));
    const uint32_t b_koff = (uint32_t)(((lane >> 3) & 1) * 16);

    int sidx = 0;
    for (int c = 0; c < nc; ++c) {
        if (c + 1 < nc) CP_WAIT1(); else CP_WAIT0();
        __syncthreads();
        if (c + 2 < nc) {
            int nidx = sidx + 2; if (nidx >= NSTAGE) nidx -= NSTAGE;
            load_stage_async(st0 + nidx * STG_BYTES, tid,
                             A, lda, mtile, W, ldw, ntile, (c + 2) * KB);
        }
        const uint32_t cur = st0 + sidx * STG_BYTES;
#pragma unroll
        for (int kc = 0; kc < 4; kc++) {
            uint32_t af[2][4], wf[4][4];
#pragma unroll
            for (int mt = 0; mt < 2; mt++) {
                uint32_t row = wm * 32 + mt * 16 + a_row;
                ldsm4(af[mt], cur + OFF_A + row * RSTRIDE + kc * 32 + a_koff);
            }
#pragma unroll
            for (int q = 0; q < 4; q++) {
                uint32_t row = wn * 64 + q * 16 + b_row;
                ldsm4(wf[q], cur + OFF_W + row * RSTRIDE + kc * 32 + b_koff);
            }
#pragma unroll
            for (int mt = 0; mt < 2; mt++)
#pragma unroll
                for (int q = 0; q < 4; q++)
#pragma unroll
                    for (int s = 0; s < 2; s++)
                        mma_f16(acc[mt][2 * q + s], af[mt], &wf[q][2 * s]);
        }
        if (++sidx >= NSTAGE) sidx = 0;
    }

    // epilogue (h16 only)
    const int g = lane >> 2, tg = lane & 3;
#pragma unroll
    for (int mt = 0; mt < 2; mt++) {
        const int m0 = mtile + wm * 32 + mt * 16 + g;
#pragma unroll
        for (int n8 = 0; n8 < 8; n8++) {
            const int nl = wn * 64 + n8 * 8 + tg * 2;
            const int n = ntile + nl;
            const float b0 = bias_s[nl], b1 = bias_s[nl + 1];
            float x0 = (acc[mt][n8][0] + b0) * scale;
            float x1 = (acc[mt][n8][1] + b1) * scale;
            float y0 = (acc[mt][n8][2] + b0) * scale;
            float y1 = (acc[mt][n8][3] + b1) * scale;
            if (ELU_) {
                x0 = x0 > 0.f ? x0 : expm1f(x0);
                x1 = x1 > 0.f ? x1 : expm1f(x1);
                y0 = y0 > 0.f ? y0 : expm1f(y0);
                y1 = y1 > 0.f ? y1 : expm1f(y1);
            }
            union { h16 h[2]; uint32_t u; } p;
            p.h[0] = __float2half_rn(x0); p.h[1] = __float2half_rn(x1);
            *(uint32_t*)(cptr + (size_t)m0 * ldc + n) = p.u;
            p.h[0] = __float2half_rn(y0); p.h[1] = __float2half_rn(y1);
            *(uint32_t*)(cptr + (size_t)(m0 + 8) * ldc + n) = p.u;
        }
    }
}

// ===========================================================================
// Attention — fp16 q/kv inputs, fp16 attn output
// ===========================================================================
__global__ void attention_kernel(const h16* __restrict__ q,
                                 const h16* __restrict__ kv,
                                 h16* __restrict__ attn,
                                 float* __restrict__ infl)
{
    const int b = blockIdx.x;
    const int tid = threadIdx.x;
    const int h = tid >> 5;
    const int lane = tid & 31;
    __shared__ float sw[H_][O_];

    const size_t base = (size_t)b * U_ + (size_t)h * HD_;
    const float4 qv = load_h4(q + base + lane * 4);

    float s[O_];
#pragma unroll
    for (int o = 0; o < O_; o++) {
        const size_t kb = ((size_t)o * B_ + b) * (2 * U_) + (size_t)h * HD_;
        const float4 kvv = load_h4(kv + kb + lane * 4);
        float d = qv.x * kvv.x + qv.y * kvv.y + qv.z * kvv.z + qv.w * kvv.w;
#pragma unroll
        for (int off = 16; off > 0; off >>= 1)
            d += __shfl_xor_sync(0xffffffffu, d, off);
        s[o] = d;
    }
    const float m = fmaxf(s[0], fmaxf(s[1], s[2]));
    const float e0 = expf(s[0] - m), e1 = expf(s[1] - m), e2 = expf(s[2] - m);
    const float inv = 1.f / (e0 + e1 + e2);
    const float w[O_] = {e0 * inv, e1 * inv, e2 * inv};

    float4 a = make_float4(0.f, 0.f, 0.f, 0.f);
#pragma unroll
    for (int o = 0; o < O_; o++) {
        const size_t vb = ((size_t)o * B_ + b) * (2 * U_) + U_ + (size_t)h * HD_;
        const float4 vv = load_h4(kv + vb + lane * 4);
        a.x = fmaf(w[o], vv.x, a.x);
        a.y = fmaf(w[o], vv.y, a.y);
        a.z = fmaf(w[o], vv.z, a.z);
        a.w = fmaf(w[o], vv.w, a.w);
    }
    {
        union { h16 h[4]; uint2 u; } uh;
        uh.h[0] = __float2half_rn(a.x); uh.h[1] = __float2half_rn(a.y);
        uh.h[2] = __float2half_rn(a.z); uh.h[3] = __float2half_rn(a.w);
        *(uint2*)(attn + base + lane * 4) = uh.u;
    }

    if (lane == 0) { sw[h][0] = w[0]; sw[h][1] = w[1]; sw[h][2] = w[2]; }
    __syncthreads();
    if (tid < O_)
        infl[(size_t)b * O_ + tid] =
            0.25f * (sw[0][tid] + sw[1][tid] + sw[2][tid] + sw[3][tid]);
}

// ===========================================================================
// Fused skinny heads — one warp per row, fp16 activations, fp32 weights
// ===========================================================================
__global__ void skinny_agent(const h16* __restrict__ ah,
                             const float* __restrict__ Wp, const float* __restrict__ bp,
                             const float* __restrict__ Wv, const float* __restrict__ bv,
                             float* __restrict__ pol, float* __restrict__ val)
{
    const int wid = threadIdx.x >> 5, lane = threadIdx.x & 31;
    const int b = blockIdx.x * 8 + wid;
    const uint4* x4 = (const uint4*)(ah + (size_t)b * U_);
    float xs[16];
    unpack8(x4[lane], xs);
    unpack8(x4[lane + 32], xs + 8);
#pragma unroll
    for (int n = 0; n < 7; n++) {
        const float4* w4 = (const float4*)((n < 6) ? (Wp + (size_t)n * U_) : Wv);
        float d = 0.f;
        float wf[8];
        *(float4*)(wf)     = w4[2 * lane];
        *(float4*)(wf + 4) = w4[2 * lane + 1];
#pragma unroll
        for (int t = 0; t < 8; t++) d += xs[t] * wf[t];
        *(float4*)(wf)     = w4[2 * (lane + 32)];
        *(float4*)(wf + 4) = w4[2 * (lane + 32) + 1];
#pragma unroll
        for (int t = 0; t < 8; t++) d += xs[8 + t] * wf[t];
#pragma unroll
        for (int off = 16; off > 0; off >>= 1) d += __shfl_xor_sync(~0u, d, off);
        if (lane == 0) {
            if (n < 6) pol[(size_t)b * A_ + n] = d + bp[n];
            else       val[b] = d + bv[0];
        }
    }
}

__global__ void skinny_opp(const h16* __restrict__ oh,
                           const float* __restrict__ W_op, const float* __restrict__ b_op,
                           const float* __restrict__ W_ov, const float* __restrict__ b_ov,
                           float* __restrict__ pol, float* __restrict__ val)
{
    const int wid = threadIdx.x >> 5, lane = threadIdx.x & 31;
    const int b = blockIdx.x * 8 + wid;
    const int o = blockIdx.y;
    const uint4* x4 = (const uint4*)(oh + ((size_t)o * B_ + b) * U_);
    float xs[16];
    unpack8(x4[lane], xs);
    unpack8(x4[lane + 32], xs + 8);
    const float* Wp = W_op + (size_t)o * A_ * U_;
    const float* Wv = W_ov + (size_t)o * U_;
#pragma unroll
    for (int n = 0; n < 7; n++) {
        const float4* w4 = (const float4*)((n < 6) ? (Wp + (size_t)n * U_) : Wv);
        float d = 0.f;
        float wf[8];
        *(float4*)(wf)     = w4[2 * lane];
        *(float4*)(wf + 4) = w4[2 * lane + 1];
#pragma unroll
        for (int t = 0; t < 8; t++) d += xs[t] * wf[t];
        *(float4*)(wf)     = w4[2 * (lane + 32)];
        *(float4*)(wf + 4) = w4[2 * (lane + 32) + 1];
#pragma unroll
        for (int t = 0; t < 8; t++) d += xs[8 + t] * wf[t];
#pragma unroll
        for (int off = 16; off > 0; off >>= 1) d += __shfl_xor_sync(~0u, d, off);
        if (lane == 0) {
            if (n < 6) pol[(size_t)b * (O_ * A_) + o * A_ + n] = d + b_op[o * A_ + n];
            else       val[(size_t)b * O_ + o] = d + b_ov[o];
        }
    }
}

// ===========================================================================
extern "C" void kernel_launch(void* const* d_in, const int* in_sizes, int n_in,
                              void* d_out, int out_size)
{
    const float* features = (const float*)d_in[0];
    const float* W_al = (const float*)d_in[1];
    const float* b_al = (const float*)d_in[2];
    const float* W_in = (const float*)d_in[3];
    const float* b_in = (const float*)d_in[4];
    const float* W_out = (const float*)d_in[5];
    const float* b_out = (const float*)d_in[6];
    const float* W_ah = (const float*)d_in[7];
    const float* b_ah = (const float*)d_in[8];
    const float* W_ap = (const float*)d_in[9];
    const float* b_ap = (const float*)d_in[10];
    const float* W_av = (const float*)d_in[11];
    const float* b_av = (const float*)d_in[12];
    const float* W_ol = (const float*)d_in[13];
    const float* b_ol = (const float*)d_in[14];
    const float* W_oh = (const float*)d_in[15];
    const float* b_oh = (const float*)d_in[16];
    const float* W_op = (const float*)d_in[17];
    const float* b_op = (const float*)d_in[18];
    const float* W_ov = (const float*)d_in[19];
    const float* b_ov = (const float*)d_in[20];
    float* out = (float*)d_out;

    h16 *feat, *cat, *opp, *attn, *q, *kv, *ah, *oh;
    h16 *Wbig, *Win, *Wout, *Wah, *Woh;
    cudaGetSymbolAddress((void**)&feat, g_feat);
    cudaGetSymbolAddress((void**)&cat, g_cat);
    cudaGetSymbolAddress((void**)&opp, g_opp);
    cudaGetSymbolAddress((void**)&attn, g_attn);
    cudaGetSymbolAddress((void**)&q, g_q);
    cudaGetSymbolAddress((void**)&kv, g_kv);
    cudaGetSymbolAddress((void**)&ah, g_ah);
    cudaGetSymbolAddress((void**)&oh, g_oh);
    cudaGetSymbolAddress((void**)&Wbig, g_Wbig);
    cudaGetSymbolAddress((void**)&Win, g_Win);
    cudaGetSymbolAddress((void**)&Wout, g_Wout);
    cudaGetSymbolAddress((void**)&Wah, g_Wah);
    cudaGetSymbolAddress((void**)&Woh, g_Woh);

    cudaFuncSetAttribute(gemm_mma<true, true>,
                         cudaFuncAttributeMaxDynamicSharedMemorySize, GEMM_SMEM);
    cudaFuncSetAttribute(gemm_mma<false, false>,
                         cudaFuncAttributeMaxDynamicSharedMemorySize, GEMM_SMEM);
    cudaFuncSetAttribute(gemm_mma<true, false>,
                         cudaFuncAttributeMaxDynamicSharedMemorySize, GEMM_SMEM);

    const float qscale = 0.08838834764831845f;  // 1/sqrt(128)

    float* out_agent_policy = out;
    float* out_agent_value  = out + (size_t)B_ * A_;
    float* out_opp_policy   = out_agent_value + B_;
    float* out_opp_value    = out_opp_policy + (size_t)B_ * O_ * A_;
    float* out_infl         = out_opp_value + (size_t)B_ * O_;

    const dim3 gb(256);

    // 0) all converts in one launch
    convert_all<<<(CTOT + 255) / 256, 256>>>(features, W_al, W_ol, W_in,
                                             W_out, W_ah, W_oh);
    // 1+2) agent_latent (z=0 -> cat[:, :U]) + opp_lat (z=1..3), merged, K=F
    gemm_mma<true, true><<<dim3(4, 64, 4), gb, GEMM_SMEM>>>(
        feat, F_, 0ull, Wbig, F_, (unsigned long long)UF_, b_al, 0, 1.f,
        cat, 2 * U_, 0ull, b_ol, F_);
    // 3) q = agent_latent @ Wq^T (reads cat[:, :U] only): K = U_
    gemm_mma<false, false><<<dim3(4, 64, 1), gb, GEMM_SMEM>>>(
        cat, 2 * U_, 0ull, Win, U_, 0ull, b_in, 0, qscale,
        q, U_, 0ull, nullptr, U_);
    // 4) k+v fused (N=1024), z=3, K=U
    gemm_mma<false, false><<<dim3(8, 64, 3), gb, GEMM_SMEM>>>(
        opp, U_, (unsigned long long)BU_,
        Win + (size_t)U_ * U_, U_, 0ull, b_in + U_, 0, 1.f,
        kv, 2 * U_, (unsigned long long)B_ * 2 * U_, nullptr, U_);
    // 5) attention
    attention_kernel<<<B_, 128>>>(q, kv, attn, out_infl);
    // 6) attn_out -> cat[:, U:], K=U
    gemm_mma<false, false><<<dim3(4, 64, 1), gb, GEMM_SMEM>>>(
        attn, U_, 0ull, Wout, U_, 0ull, b_out, 0, 1.f,
        cat + U_, 2 * U_, 0ull, nullptr, U_);
    // 7) agent_head, K = 2U (both cat halves written earlier this run)
    gemm_mma<true, false><<<dim3(4, 64, 1), gb, GEMM_SMEM>>>(
        cat, 2 * U_, 0ull, Wah, 2 * U_, 0ull, b_ah, 0, 1.f,
        ah, U_, 0ull, nullptr, 2 * U_);
    // 8) agent policy + value
    skinny_agent<<<B_ / 8, 256>>>(ah, W_ap, b_ap, W_av, b_av,
                                  out_agent_policy, out_agent_value);
    // 9) opp_heads (z=3), K=U
    gemm_mma<true, false><<<dim3(4, 64, 3), gb, GEMM_SMEM>>>(
        opp, U_, (unsigned long long)BU_,
        Woh, U_, (unsigned long long)((size_t)U_ * U_), b_oh, U_, 1.f,
        oh, U_, (unsigned long long)BU_, nullptr, U_);
    // 10) opponent policies + values
    skinny_opp<<<dim3(B_ / 8, 3), 256>>>(oh, W_op, b_op, W_ov, b_ov,
                                         out_opp_policy, out_opp_value);
}

// round 10
// speedup vs baseline: 1.4848x; 1.0554x over previous
#include <cuda_runtime.h>
#include <cuda_fp16.h>
#include <math.h>
#include <stdint.h>

// Problem constants
#define B_ 8192
#define F_ 1024
#define U_ 512
#define O_ 3
#define A_ 6
#define H_ 4
#define HD_ 128

typedef __half h16;
#define BU_ ((size_t)B_ * U_)
#define UF_ ((size_t)U_ * F_)

// ===========================================================================
// Scratch (device globals) — all activations fp16
// ===========================================================================
__device__ __align__(128) h16 g_feat[(size_t)B_ * F_];
__device__ __align__(128) h16 g_cat[(size_t)B_ * 2 * U_];     // [agent_latent | attn_out]
__device__ __align__(128) h16 g_opp[(size_t)O_ * B_ * U_];
__device__ __align__(128) h16 g_attn[(size_t)B_ * U_];
__device__ __align__(128) h16 g_q[(size_t)B_ * U_];
__device__ __align__(128) h16 g_kv[(size_t)O_ * B_ * 2 * U_]; // [O][B][k|v]
__device__ __align__(128) h16 g_ah[(size_t)B_ * U_];
__device__ __align__(128) h16 g_oh[(size_t)O_ * B_ * U_];
// weights (fp16); Wbig = [W_al | W_ol(3)] packed, z-stride U*F
__device__ __align__(128) h16 g_Wbig[(size_t)4 * U_ * F_];
__device__ __align__(128) h16 g_Win[(size_t)3 * U_ * U_];
__device__ __align__(128) h16 g_Wout[(size_t)U_ * U_];
__device__ __align__(128) h16 g_Wah[(size_t)U_ * 2 * U_];
__device__ __align__(128) h16 g_Woh[(size_t)O_ * U_ * U_];

// ===========================================================================
// PTX helpers
// ===========================================================================
__device__ __forceinline__ uint32_t smem_u32(const void* p) {
    uint32_t a;
    asm("{ .reg .u64 t; cvta.to.shared.u64 t, %1; cvt.u32.u64 %0, t; }"
        : "=r"(a) : "l"(p));
    return a;
}
__device__ __forceinline__ void cp16(uint32_t s, const void* g) {
    asm volatile("cp.async.cg.shared.global [%0], [%1], 16;" :: "r"(s), "l"(g));
}
#define CP_COMMIT() asm volatile("cp.async.commit_group;" ::: "memory")
#define CP_WAIT0()  asm volatile("cp.async.wait_group 0;" ::: "memory")
#define CP_WAIT1()  asm volatile("cp.async.wait_group 1;" ::: "memory")

__device__ __forceinline__ void ldsm4(uint32_t* r, uint32_t addr) {
    asm volatile("ldmatrix.sync.aligned.m8n8.x4.shared.b16 {%0,%1,%2,%3}, [%4];"
                 : "=r"(r[0]), "=r"(r[1]), "=r"(r[2]), "=r"(r[3]) : "r"(addr));
}
__device__ __forceinline__ void mma_f16(float* c, const uint32_t* a, const uint32_t* b) {
    asm volatile("mma.sync.aligned.m16n8k16.row.col.f32.f16.f16.f32 "
                 "{%0,%1,%2,%3}, {%4,%5,%6,%7}, {%8,%9}, {%0,%1,%2,%3};"
                 : "+f"(c[0]), "+f"(c[1]), "+f"(c[2]), "+f"(c[3])
                 : "r"(a[0]), "r"(a[1]), "r"(a[2]), "r"(a[3]),
                   "r"(b[0]), "r"(b[1]));
}
__device__ __forceinline__ void unpack8(uint4 u, float* out) {
    const __half2* h = (const __half2*)&u;
#pragma unroll
    for (int j = 0; j < 4; j++) {
        float2 f = __half22float2(h[j]);
        out[2 * j] = f.x; out[2 * j + 1] = f.y;
    }
}
__device__ __forceinline__ float4 load_h4(const h16* p) {
    uint2 u = *(const uint2*)p;
    const __half2* h = (const __half2*)&u;
    float2 a = __half22float2(h[0]), b = __half22float2(h[1]);
    return make_float4(a.x, a.y, b.x, b.y);
}

// ===========================================================================
// One-shot convert: features + all weights, flat index + segment chain
// ===========================================================================
#define CN0 ((int)((size_t)B_ * F_ / 4))
#define CN1 ((int)(UF_ / 4))
#define CN2 ((int)(3 * UF_ / 4))
#define CN3 ((int)(3 * (size_t)U_ * U_ / 4))
#define CN4 ((int)((size_t)U_ * U_ / 4))
#define CN5 ((int)(2 * (size_t)U_ * U_ / 4))
#define CN6 ((int)(3 * (size_t)U_ * U_ / 4))
#define CTOT (CN0 + CN1 + CN2 + CN3 + CN4 + CN5 + CN6)

__global__ void convert_all(const float* __restrict__ f,
                            const float* __restrict__ wal,
                            const float* __restrict__ wol,
                            const float* __restrict__ win,
                            const float* __restrict__ wout,
                            const float* __restrict__ wah,
                            const float* __restrict__ woh)
{
    int i = blockIdx.x * blockDim.x + threadIdx.x;
    if (i >= CTOT) return;
    const float* src; h16* dst; int off;
    if (i < CN0)                 { src = f;    dst = g_feat;        off = i; }
    else if ((i -= CN0) < CN1)   { src = wal;  dst = g_Wbig;        off = i; }
    else if ((i -= CN1) < CN2)   { src = wol;  dst = g_Wbig + UF_;  off = i; }
    else if ((i -= CN2) < CN3)   { src = win;  dst = g_Win;         off = i; }
    else if ((i -= CN3) < CN4)   { src = wout; dst = g_Wout;        off = i; }
    else if ((i -= CN4) < CN5)   { src = wah;  dst = g_Wah;         off = i; }
    else                         { src = woh;  dst = g_Woh;         off = i - CN5; }
    float4 x = ((const float4*)src)[off];
    h16 h[4] = {__float2half_rn(x.x), __float2half_rn(x.y),
                __float2half_rn(x.z), __float2half_rn(x.w)};
    ((uint2*)dst)[off] = *(uint2*)h;
}

// ===========================================================================
// GEMM core (inlined): C(h16) = act((A @ W^T + bias) * scale)
// CTA 128x128, 8 warps (4Mx2N), K chunk = 64, 3-stage cp.async ring, occ 2.
// ===========================================================================
#define MT 128
#define NT 128
#define KB 64
#define RSTRIDE 144
#define COMP_BYTES (128 * RSTRIDE)
#define OFF_A 0
#define OFF_W COMP_BYTES
#define STG_BYTES (2 * COMP_BYTES)
#define NSTAGE 3
#define GEMM_SMEM (1024 + NSTAGE * STG_BYTES)   // 111616

__device__ __forceinline__ void load_stage_async(
    uint32_t st, int tid,
    const h16* __restrict__ A, int lda, int mtile,
    const h16* __restrict__ W, int ldw, int ntile, int k0)
{
#pragma unroll
    for (int i = 0; i < 4; i++) {
        int idx = tid + i * 256;
        int r = idx >> 3, c = idx & 7;
        uint32_t so = (uint32_t)(r * RSTRIDE + c * 16);
        cp16(st + OFF_A + so, A + (size_t)(mtile + r) * lda + k0 + c * 8);
    }
#pragma unroll
    for (int i = 0; i < 4; i++) {
        int idx = tid + i * 256;
        int r = idx >> 3, c = idx & 7;
        uint32_t so = (uint32_t)(r * RSTRIDE + c * 16);
        cp16(st + OFF_W + so, W + (size_t)(ntile + r) * ldw + k0 + c * 8);
    }
    CP_COMMIT();
}

__device__ __forceinline__ void gemm_core(
    const h16* __restrict__ A, int lda,
    const h16* __restrict__ W, int ldw,
    const float* __restrict__ bias, float scale,
    h16* __restrict__ C, int ldc,
    int K, bool elu, char* smem)
{
    float* bias_s = (float*)smem;
    const uint32_t st0 = smem_u32(smem + 1024);

    const int tid = threadIdx.x, lane = tid & 31, wid = tid >> 5;
    const int wm = wid & 3, wn = wid >> 2;
    const int mtile = blockIdx.y * MT;
    const int ntile = blockIdx.x * NT;

    if (tid < NT) bias_s[tid] = bias[ntile + tid];

    float acc[2][8][4];
#pragma unroll
    for (int i = 0; i < 2; i++)
#pragma unroll
        for (int j = 0; j < 8; j++)
#pragma unroll
            for (int t = 0; t < 4; t++) acc[i][j][t] = 0.f;

    const int nc = K / KB;

    load_stage_async(st0, tid, A, lda, mtile, W, ldw, ntile, 0);
    load_stage_async(st0 + STG_BYTES, tid, A, lda, mtile, W, ldw, ntile, KB);

    const uint32_t a_row = (uint32_t)(lane & 15);
    const uint32_t a_koff = (uint32_t)((lane >> 4) * 16);
    const uint32_t b_row = (uint32_t)(((lane >> 4) * 8) + (lane & 7));
    const uint32_t b_koff = (uint32_t)(((lane >> 3) & 1) * 16);

    int sidx = 0;
    for (int c = 0; c < nc; ++c) {
        if (c + 1 < nc) CP_WAIT1(); else CP_WAIT0();
        __syncthreads();
        if (c + 2 < nc) {
            int nidx = sidx + 2; if (nidx >= NSTAGE) nidx -= NSTAGE;
            load_stage_async(st0 + nidx * STG_BYTES, tid,
                             A, lda, mtile, W, ldw, ntile, (c + 2) * KB);
        }
        const uint32_t cur = st0 + sidx * STG_BYTES;
#pragma unroll
        for (int kc = 0; kc < 4; kc++) {
            uint32_t af[2][4], wf[4][4];
#pragma unroll
            for (int mt = 0; mt < 2; mt++) {
                uint32_t row = wm * 32 + mt * 16 + a_row;
                ldsm4(af[mt], cur + OFF_A + row * RSTRIDE + kc * 32 + a_koff);
            }
#pragma unroll
            for (int q = 0; q < 4; q++) {
                uint32_t row = wn * 64 + q * 16 + b_row;
                ldsm4(wf[q], cur + OFF_W + row * RSTRIDE + kc * 32 + b_koff);
            }
#pragma unroll
            for (int mt = 0; mt < 2; mt++)
#pragma unroll
                for (int q = 0; q < 4; q++)
#pragma unroll
                    for (int s = 0; s < 2; s++)
                        mma_f16(acc[mt][2 * q + s], af[mt], &wf[q][2 * s]);
        }
        if (++sidx >= NSTAGE) sidx = 0;
    }

    const int g = lane >> 2, tg = lane & 3;
#pragma unroll
    for (int mt = 0; mt < 2; mt++) {
        const int m0 = mtile + wm * 32 + mt * 16 + g;
#pragma unroll
        for (int n8 = 0; n8 < 8; n8++) {
            const int nl = wn * 64 + n8 * 8 + tg * 2;
            const int n = ntile + nl;
            const float b0 = bias_s[nl], b1 = bias_s[nl + 1];
            float x0 = (acc[mt][n8][0] + b0) * scale;
            float x1 = (acc[mt][n8][1] + b1) * scale;
            float y0 = (acc[mt][n8][2] + b0) * scale;
            float y1 = (acc[mt][n8][3] + b1) * scale;
            if (elu) {
                x0 = x0 > 0.f ? x0 : expm1f(x0);
                x1 = x1 > 0.f ? x1 : expm1f(x1);
                y0 = y0 > 0.f ? y0 : expm1f(y0);
                y1 = y1 > 0.f ? y1 : expm1f(y1);
            }
            union { h16 h[2]; uint32_t u; } p;
            p.h[0] = __float2half_rn(x0); p.h[1] = __float2half_rn(x1);
            *(uint32_t*)(C + (size_t)m0 * ldc + n) = p.u;
            p.h[0] = __float2half_rn(y0); p.h[1] = __float2half_rn(y1);
            *(uint32_t*)(C + (size_t)(m0 + 8) * ldc + n) = p.u;
        }
    }
}

// ---- mode wrappers ----
// G1: z=0 agent_latent -> cat[:, :U]; z=1..3 opp_lat.  grid (4, 64, 4)
__global__ void __launch_bounds__(256, 2)
gemm_k1(const float* __restrict__ b_al, const float* __restrict__ b_ol)
{
    extern __shared__ __align__(128) char smem[];
    const int z = blockIdx.z;
    if (z == 0)
        gemm_core(g_feat, F_, g_Wbig, F_, b_al, 1.f,
                  g_cat, 2 * U_, F_, true, smem);
    else
        gemm_core(g_feat, F_, g_Wbig + (size_t)z * UF_, F_,
                  b_ol + (size_t)(z - 1) * U_, 1.f,
                  g_opp + (size_t)(z - 1) * BU_, U_, F_, true, smem);
}

// QKV: z=0 q (N=512: blockIdx.x<4), z=1..3 kv (N=1024).  grid (8, 64, 4)
__global__ void __launch_bounds__(256, 2)
gemm_qkv(const float* __restrict__ b_in, float qscale)
{
    extern __shared__ __align__(128) char smem[];
    const int z = blockIdx.z;
    if (z == 0) {
        if (blockIdx.x >= 4) return;
        gemm_core(g_cat, 2 * U_, g_Win, U_, b_in, qscale,
                  g_q, U_, U_, false, smem);
    } else {
        gemm_core(g_opp + (size_t)(z - 1) * BU_, U_,
                  g_Win + (size_t)U_ * U_, U_, b_in + U_, 1.f,
                  g_kv + (size_t)(z - 1) * B_ * 2 * U_, 2 * U_, U_, false, smem);
    }
}

// AO: z=0 attn_out -> cat[:, U:] (no ELU); z=1..3 opp_heads (ELU). grid (4,64,4)
__global__ void __launch_bounds__(256, 2)
gemm_ao(const float* __restrict__ b_out, const float* __restrict__ b_oh)
{
    extern __shared__ __align__(128) char smem[];
    const int z = blockIdx.z;
    if (z == 0)
        gemm_core(g_attn, U_, g_Wout, U_, b_out, 1.f,
                  g_cat + U_, 2 * U_, U_, false, smem);
    else
        gemm_core(g_opp + (size_t)(z - 1) * BU_, U_,
                  g_Woh + (size_t)(z - 1) * U_ * U_, U_,
                  b_oh + (size_t)(z - 1) * U_, 1.f,
                  g_oh + (size_t)(z - 1) * BU_, U_, U_, true, smem);
}

// AH: agent_head, K = 2U.  grid (4, 64, 1)
__global__ void __launch_bounds__(256, 2)
gemm_ah(const float* __restrict__ b_ah)
{
    extern __shared__ __align__(128) char smem[];
    gemm_core(g_cat, 2 * U_, g_Wah, 2 * U_, b_ah, 1.f,
              g_ah, U_, 2 * U_, true, smem);
}

// ===========================================================================
// Attention — 2 rows per 256-thread CTA, warp = (row, head)
// ===========================================================================
__global__ void attention_kernel(float* __restrict__ infl)
{
    const int tid = threadIdx.x;
    const int sub = tid >> 7;                 // which of 2 rows
    const int ltid = tid & 127;
    const int b = blockIdx.x * 2 + sub;
    const int h = ltid >> 5;
    const int lane = tid & 31;
    __shared__ float sw[2][H_][O_];

    const size_t base = (size_t)b * U_ + (size_t)h * HD_;
    const float4 qv = load_h4(g_q + base + lane * 4);

    float s[O_];
#pragma unroll
    for (int o = 0; o < O_; o++) {
        const size_t kb = ((size_t)o * B_ + b) * (2 * U_) + (size_t)h * HD_;
        const float4 kvv = load_h4(g_kv + kb + lane * 4);
        float d = qv.x * kvv.x + qv.y * kvv.y + qv.z * kvv.z + qv.w * kvv.w;
#pragma unroll
        for (int off = 16; off > 0; off >>= 1)
            d += __shfl_xor_sync(0xffffffffu, d, off);
        s[o] = d;
    }
    const float m = fmaxf(s[0], fmaxf(s[1], s[2]));
    const float e0 = expf(s[0] - m), e1 = expf(s[1] - m), e2 = expf(s[2] - m);
    const float inv = 1.f / (e0 + e1 + e2);
    const float w[O_] = {e0 * inv, e1 * inv, e2 * inv};

    float4 a = make_float4(0.f, 0.f, 0.f, 0.f);
#pragma unroll
    for (int o = 0; o < O_; o++) {
        const size_t vb = ((size_t)o * B_ + b) * (2 * U_) + U_ + (size_t)h * HD_;
        const float4 vv = load_h4(g_kv + vb + lane * 4);
        a.x = fmaf(w[o], vv.x, a.x);
        a.y = fmaf(w[o], vv.y, a.y);
        a.z = fmaf(w[o], vv.z, a.z);
        a.w = fmaf(w[o], vv.w, a.w);
    }
    {
        union { h16 h[4]; uint2 u; } uh;
        uh.h[0] = __float2half_rn(a.x); uh.h[1] = __float2half_rn(a.y);
        uh.h[2] = __float2half_rn(a.z); uh.h[3] = __float2half_rn(a.w);
        *(uint2*)(g_attn + base + lane * 4) = uh.u;
    }

    if (lane == 0) {
        sw[sub][h][0] = w[0]; sw[sub][h][1] = w[1]; sw[sub][h][2] = w[2];
    }
    __syncthreads();
    if (ltid < O_)
        infl[(size_t)b * O_ + ltid] =
            0.25f * (sw[sub][0][ltid] + sw[sub][1][ltid] +
                     sw[sub][2][ltid] + sw[sub][3][ltid]);
}

// ===========================================================================
// Fused skinny heads — grid (B/8, 4): y=0 agent (g_ah), y>0 opp o=y-1 (g_oh)
// ===========================================================================
__global__ void skinny_all(const float* __restrict__ W_ap, const float* __restrict__ b_ap,
                           const float* __restrict__ W_av, const float* __restrict__ b_av,
                           const float* __restrict__ W_op, const float* __restrict__ b_op,
                           const float* __restrict__ W_ov, const float* __restrict__ b_ov,
                           float* __restrict__ agent_pol, float* __restrict__ agent_val,
                           float* __restrict__ opp_pol, float* __restrict__ opp_val)
{
    const int wid = threadIdx.x >> 5, lane = threadIdx.x & 31;
    const int b = blockIdx.x * 8 + wid;
    const int y = blockIdx.y;

    const h16* act; const float *Wp, *bp, *Wv, *bv;
    if (y == 0) {
        act = g_ah + (size_t)b * U_;
        Wp = W_ap; bp = b_ap; Wv = W_av; bv = b_av;
    } else {
        const int o = y - 1;
        act = g_oh + ((size_t)o * B_ + b) * U_;
        Wp = W_op + (size_t)o * A_ * U_; bp = b_op + o * A_;
        Wv = W_ov + (size_t)o * U_;      bv = b_ov + o;
    }

    const uint4* x4 = (const uint4*)act;
    float xs[16];
    unpack8(x4[lane], xs);
    unpack8(x4[lane + 32], xs + 8);
#pragma unroll
    for (int n = 0; n < 7; n++) {
        const float4* w4 = (const float4*)((n < 6) ? (Wp + (size_t)n * U_) : Wv);
        float d = 0.f;
        float wf[8];
        *(float4*)(wf)     = w4[2 * lane];
        *(float4*)(wf + 4) = w4[2 * lane + 1];
#pragma unroll
        for (int t = 0; t < 8; t++) d += xs[t] * wf[t];
        *(float4*)(wf)     = w4[2 * (lane + 32)];
        *(float4*)(wf + 4) = w4[2 * (lane + 32) + 1];
#pragma unroll
        for (int t = 0; t < 8; t++) d += xs[8 + t] * wf[t];
#pragma unroll
        for (int off = 16; off > 0; off >>= 1) d += __shfl_xor_sync(~0u, d, off);
        if (lane == 0) {
            if (y == 0) {
                if (n < 6) agent_pol[(size_t)b * A_ + n] = d + bp[n];
                else       agent_val[b] = d + bv[0];
            } else {
                const int o = y - 1;
                if (n < 6) opp_pol[(size_t)b * (O_ * A_) + o * A_ + n] = d + bp[n];
                else       opp_val[(size_t)b * O_ + o] = d + bv[0];
            }
        }
    }
}

// ===========================================================================
extern "C" void kernel_launch(void* const* d_in, const int* in_sizes, int n_in,
                              void* d_out, int out_size)
{
    const float* features = (const float*)d_in[0];
    const float* W_al = (const float*)d_in[1];
    const float* b_al = (const float*)d_in[2];
    const float* W_in = (const float*)d_in[3];
    const float* b_in = (const float*)d_in[4];
    const float* W_out = (const float*)d_in[5];
    const float* b_out = (const float*)d_in[6];
    const float* W_ah = (const float*)d_in[7];
    const float* b_ah = (const float*)d_in[8];
    const float* W_ap = (const float*)d_in[9];
    const float* b_ap = (const float*)d_in[10];
    const float* W_av = (const float*)d_in[11];
    const float* b_av = (const float*)d_in[12];
    const float* W_ol = (const float*)d_in[13];
    const float* b_ol = (const float*)d_in[14];
    const float* W_oh = (const float*)d_in[15];
    const float* b_oh = (const float*)d_in[16];
    const float* W_op = (const float*)d_in[17];
    const float* b_op = (const float*)d_in[18];
    const float* W_ov = (const float*)d_in[19];
    const float* b_ov = (const float*)d_in[20];
    float* out = (float*)d_out;

    cudaFuncSetAttribute(gemm_k1,
                         cudaFuncAttributeMaxDynamicSharedMemorySize, GEMM_SMEM);
    cudaFuncSetAttribute(gemm_qkv,
                         cudaFuncAttributeMaxDynamicSharedMemorySize, GEMM_SMEM);
    cudaFuncSetAttribute(gemm_ao,
                         cudaFuncAttributeMaxDynamicSharedMemorySize, GEMM_SMEM);
    cudaFuncSetAttribute(gemm_ah,
                         cudaFuncAttributeMaxDynamicSharedMemorySize, GEMM_SMEM);

    const float qscale = 0.08838834764831845f;  // 1/sqrt(128)

    float* out_agent_policy = out;
    float* out_agent_value  = out + (size_t)B_ * A_;
    float* out_opp_policy   = out_agent_value + B_;
    float* out_opp_value    = out_opp_policy + (size_t)B_ * O_ * A_;
    float* out_infl         = out_opp_value + (size_t)B_ * O_;

    const dim3 gb(256);

    // 0) all converts in one launch
    convert_all<<<(CTOT + 255) / 256, 256>>>(features, W_al, W_ol, W_in,
                                             W_out, W_ah, W_oh);
    // 1) agent_latent + opp_lat (merged z=4)
    gemm_k1<<<dim3(4, 64, 4), gb, GEMM_SMEM>>>(b_al, b_ol);
    // 2) q + kv (merged z=4)
    gemm_qkv<<<dim3(8, 64, 4), gb, GEMM_SMEM>>>(b_in, qscale);
    // 3) attention (+ influences)
    attention_kernel<<<B_ / 2, 256>>>(out_infl);
    // 4) attn_out + opp_heads (merged z=4)
    gemm_ao<<<dim3(4, 64, 4), gb, GEMM_SMEM>>>(b_out, b_oh);
    // 5) agent_head
    gemm_ah<<<dim3(4, 64, 1), gb, GEMM_SMEM>>>(b_ah);
    // 6) all skinny heads (merged)
    skinny_all<<<dim3(B_ / 8, 4), 256>>>(W_ap, b_ap, W_av, b_av,
                                         W_op, b_op, W_ov, b_ov,
                                         out_agent_policy, out_agent_value,
                                         out_opp_policy, out_opp_value);
}